// round 8
// baseline (speedup 1.0000x reference)
#include <cuda_runtime.h>
#include <cuda_bf16.h>
#include <cstdint>

// RBF-kernel causal attention via warp-level mma.sync (bf16, hi/lo compensated).
// Round 8: BM=128 (32 query rows per warp, 2 row-blocks -> 2x MMA per ldsm and
// 2x accumulator ILP), ping-pong prefetched ldsm, prep kernel + cp.async double
// buffer as R7. B=2, H=16, N=2048, D=64.

#define N_   2048
#define D_   64
#define BM   128
#define BN   64
#define NTH  128
#define LDH  72                      // halves per bf16 smem row (144 B)
#define CEXP 0.18033688011112042f    // log2(e)/8

#define MAT    9216                  // 64 rows * 144 B
#define B_KH   0
#define B_KL   MAT
#define B_VH   (2*MAT)
#define B_VL   (3*MAT)
#define B_KSQ  (4*MAT)
#define BUF    (4*MAT + 256)         // 37120
#define OFF_QSQ (2*BUF)              // 74240  (128 floats)
#define SMEM_BYTES (OFF_QSQ + 512)   // 74752

#define TOT4 (2*16*2048*16)          // float4 count per tensor

typedef uint32_t u32;

__device__ uint2 g_KH[TOT4];
__device__ uint2 g_KL[TOT4];
__device__ uint2 g_VH[TOT4];
__device__ uint2 g_VL[TOT4];
__device__ float g_ksq[2*16*2048];

__device__ __forceinline__ u32 smem_u32(const void* p) {
    u32 a;
    asm("{ .reg .u64 t; cvta.to.shared.u64 t, %1; cvt.u32.u64 %0, t; }"
        : "=r"(a) : "l"(p));
    return a;
}
__device__ __forceinline__ float ex2(float x) {
    float y; asm("ex2.approx.f32 %0, %1;" : "=f"(y) : "f"(x)); return y;
}
__device__ __forceinline__ void cp16(u32 saddr, const void* g) {
    asm volatile("cp.async.cg.shared.global [%0], [%1], 16;"
                 :: "r"(saddr), "l"(g) : "memory");
}
__device__ __forceinline__ void cp_commit() {
    asm volatile("cp.async.commit_group;" ::: "memory");
}
__device__ __forceinline__ void cp_wait0() {
    asm volatile("cp.async.wait_group 0;" ::: "memory");
}
__device__ __forceinline__ void ldsm4(u32 addr, u32 r[4]) {
    asm volatile("ldmatrix.sync.aligned.m8n8.x4.shared.b16 {%0,%1,%2,%3}, [%4];"
                 : "=r"(r[0]), "=r"(r[1]), "=r"(r[2]), "=r"(r[3]) : "r"(addr));
}
__device__ __forceinline__ void ldsm4t(u32 addr, u32 r[4]) {
    asm volatile("ldmatrix.sync.aligned.m8n8.x4.trans.shared.b16 {%0,%1,%2,%3}, [%4];"
                 : "=r"(r[0]), "=r"(r[1]), "=r"(r[2]), "=r"(r[3]) : "r"(addr));
}
__device__ __forceinline__ void mma16816(float d[4], const u32 a[4], u32 b0, u32 b1) {
    asm volatile(
        "mma.sync.aligned.m16n8k16.row.col.f32.bf16.bf16.f32 "
        "{%0,%1,%2,%3}, {%4,%5,%6,%7}, {%8,%9}, {%0,%1,%2,%3};"
        : "+f"(d[0]), "+f"(d[1]), "+f"(d[2]), "+f"(d[3])
        : "r"(a[0]), "r"(a[1]), "r"(a[2]), "r"(a[3]), "r"(b0), "r"(b1));
}
__device__ __forceinline__ u32 bits2(__nv_bfloat162 h) { return *(u32*)&h; }

__device__ __forceinline__ void split4(float4 v, uint2& hi, uint2& lo) {
    __nv_bfloat162 h0 = __floats2bfloat162_rn(v.x, v.y);
    __nv_bfloat162 h1 = __floats2bfloat162_rn(v.z, v.w);
    float2 f0 = __bfloat1622float2(h0);
    float2 f1 = __bfloat1622float2(h1);
    __nv_bfloat162 l0 = __floats2bfloat162_rn(v.x - f0.x, v.y - f0.y);
    __nv_bfloat162 l1 = __floats2bfloat162_rn(v.z - f1.x, v.w - f1.y);
    hi = make_uint2(bits2(h0), bits2(h1));
    lo = make_uint2(bits2(l0), bits2(l1));
}
__device__ __forceinline__ void cvt_store(char* smc, int off_hi, int off_lo, float4 v) {
    uint2 hi, lo;
    split4(v, hi, lo);
    *(uint2*)(smc + off_hi) = hi;
    *(uint2*)(smc + off_lo) = lo;
}

// ---------------- prep: f32 K/V -> bf16 hi/lo globals + ksq ----------------
__global__ void __launch_bounds__(256)
prep_kernel(const float* __restrict__ K, const float* __restrict__ V)
{
    const int i = blockIdx.x * 256 + threadIdx.x;     // float4 index
    float4 k = ((const float4*)K)[i];
    float4 v = ((const float4*)V)[i];
    uint2 hi, lo;
    split4(k, hi, lo);
    g_KH[i] = hi; g_KL[i] = lo;
    split4(v, hi, lo);
    g_VH[i] = hi; g_VL[i] = lo;

    float s = fmaf(k.x, k.x, fmaf(k.y, k.y, fmaf(k.z, k.z, k.w * k.w)));
    s += __shfl_xor_sync(0xffffffffu, s, 1, 16);
    s += __shfl_xor_sync(0xffffffffu, s, 2, 16);
    s += __shfl_xor_sync(0xffffffffu, s, 4, 16);
    s += __shfl_xor_sync(0xffffffffu, s, 8, 16);
    if ((threadIdx.x & 15) == 0) g_ksq[i >> 4] = s;
}

// cp.async one full key-tile (KH,KL,VH,VL + ksq) into smem buffer at dst
__device__ __forceinline__ void cp_tile(u32 dst, size_t rowbase, int tid)
{
    const char* khg = (const char*)g_KH + rowbase * 128;
    const char* klg = (const char*)g_KL + rowbase * 128;
    const char* vhg = (const char*)g_VH + rowbase * 128;
    const char* vlg = (const char*)g_VL + rowbase * 128;
#pragma unroll
    for (int i = 0; i < 4; i++) {
        int c   = i * 128 + tid;        // 0..511
        int row = c >> 3;
        int c8  = c & 7;
        u32 so  = (u32)(row * 144 + c8 * 16);
        size_t go = (size_t)row * 128 + (size_t)c8 * 16;
        cp16(dst + B_KH + so, khg + go);
        cp16(dst + B_KL + so, klg + go);
        cp16(dst + B_VH + so, vhg + go);
        cp16(dst + B_VL + so, vlg + go);
    }
    if (tid < 16)
        cp16(dst + B_KSQ + (u32)(tid * 16), (const char*)(g_ksq + rowbase) + tid * 16);
}

// ---------------- main kernel ----------------
__global__ void __launch_bounds__(NTH, 2)
rbf_attn_mma(const float* __restrict__ Qg, float* __restrict__ Og)
{
    extern __shared__ char smc[];
    const u32 sb  = smem_u32(smc);
    const int tid = threadIdx.x;
    const int w   = tid >> 5;
    const int t   = tid & 31;
    const int bh  = blockIdx.y;
    const int qt  = (gridDim.x - 1) - blockIdx.x;    // heavy tiles first
    const int m0  = qt * BM;
    const int nkt = 2 * qt + 2;

    const float* Qh = Qg + (size_t)bh * N_ * D_;
    float*       Oh = Og + (size_t)bh * N_ * D_;

    // ---- prologue: cp tile 0 into buffer 0 ----
    cp_tile(sb, (size_t)bh * N_, tid);
    cp_commit();

    // ---- stage Q (hi/lo bf16, 128 rows) into buffer 1, compute qsq ----
    {
        const float4* Q4 = (const float4*)(Qh + (size_t)m0 * D_);
#pragma unroll
        for (int i = 0; i < 16; i++) {
            int fidx = i * NTH + tid;
            int row  = fidx >> 4;
            int c4   = (fidx & 15) << 2;
            cvt_store(smc, BUF + (row * LDH + c4) * 2,
                           BUF + 18432 + (row * LDH + c4) * 2, Q4[fidx]);
        }
        {
            float s = 0.f;
            const float4* Qr = (const float4*)(Qh + (size_t)(m0 + tid) * D_);
#pragma unroll
            for (int j = 0; j < 16; j++) {
                float4 v = Qr[j];
                s = fmaf(v.x, v.x, fmaf(v.y, v.y, fmaf(v.z, v.z, fmaf(v.w, v.w, s))));
            }
            ((float*)(smc + OFF_QSQ))[tid] = s;
        }
    }
    __syncthreads();

    // ---- extract Q A-fragments: 2 row-blocks x 4 k-chunks ----
    u32 qa[2][4][4], ql[2][4][4];
#pragma unroll
    for (int rb = 0; rb < 2; rb++) {
        const int row = w * 32 + rb * 16 + (((t >> 3) & 1) << 3) + (t & 7);
        const int cg  = (t >> 4) << 3;
#pragma unroll
        for (int kc = 0; kc < 4; kc++) {
            u32 addr = sb + BUF + (u32)((row * LDH + 16 * kc + cg) * 2);
            ldsm4(addr, qa[rb][kc]);
            ldsm4(addr + 18432, ql[rb][kc]);
        }
    }
    float qs[2][2];
    int   m_r[2][2];
#pragma unroll
    for (int rb = 0; rb < 2; rb++) {
        qs[rb][0] = ((float*)(smc + OFF_QSQ))[w * 32 + rb * 16 + (t >> 2)];
        qs[rb][1] = ((float*)(smc + OFF_QSQ))[w * 32 + rb * 16 + (t >> 2) + 8];
        m_r[rb][0] = m0 + w * 32 + rb * 16 + (t >> 2);
        m_r[rb][1] = m_r[rb][0] + 8;
    }

    float o[2][8][4];
#pragma unroll
    for (int rb = 0; rb < 2; rb++)
#pragma unroll
        for (int i = 0; i < 8; i++)
#pragma unroll
            for (int j = 0; j < 4; j++) o[rb][i][j] = 0.f;
    float l[2][2] = {{0.f, 0.f}, {0.f, 0.f}};

    for (int kt = 0; kt < nkt; kt++) {
        const int n0 = kt * BN;
        const u32 cb = sb + (u32)((kt & 1) * BUF);
        const char* cc = smc + (size_t)((kt & 1) * BUF);

        cp_wait0();
        __syncthreads();

        if (kt + 1 < nkt)
            cp_tile(sb + (u32)(((kt + 1) & 1) * BUF),
                    (size_t)bh * N_ + (size_t)(n0 + BN), tid);
        cp_commit();

        // ---- S = Q.K^T : 16 groups x 12 MMAs, ping-pong prefetched ldsm ----
        float s[2][8][4];
#pragma unroll
        for (int rb = 0; rb < 2; rb++)
#pragma unroll
            for (int i = 0; i < 8; i++)
#pragma unroll
                for (int j = 0; j < 4; j++) s[rb][i][j] = 0.f;

        u32 kb[2][4], kl[2][4];
        {
            u32 a0 = cb + (u32)((((t & 7)) * LDH + ((t >> 3) << 3)) * 2);
            ldsm4(a0, kb[0]);
            ldsm4(a0 + MAT, kl[0]);
        }
#pragma unroll
        for (int idx = 0; idx < 16; idx++) {
            const int cur = idx & 1;
            if (idx < 15) {
                const int nn = (idx + 1) >> 1, ng = (idx + 1) & 1;
                u32 an = cb + (u32)(((8 * nn + (t & 7)) * LDH
                                     + 32 * ng + ((t >> 3) << 3)) * 2);
                ldsm4(an, kb[cur ^ 1]);
                ldsm4(an + MAT, kl[cur ^ 1]);
            }
            const int nb = idx >> 1, g = idx & 1;
#pragma unroll
            for (int rb = 0; rb < 2; rb++) {
                mma16816(s[rb][nb], qa[rb][2*g],   kb[cur][0], kb[cur][1]);
                mma16816(s[rb][nb], qa[rb][2*g+1], kb[cur][2], kb[cur][3]);
                mma16816(s[rb][nb], qa[rb][2*g],   kl[cur][0], kl[cur][1]);
                mma16816(s[rb][nb], qa[rb][2*g+1], kl[cur][2], kl[cur][3]);
                mma16816(s[rb][nb], ql[rb][2*g],   kb[cur][0], kb[cur][1]);
                mma16816(s[rb][nb], ql[rb][2*g+1], kb[cur][2], kb[cur][3]);
            }
        }

        // ---- softmax: s -> p (in place), accumulate l ----
        const bool diag = (kt >= 2 * qt);
        const float* ksq = (const float*)(cc + B_KSQ);
#pragma unroll
        for (int rb = 0; rb < 2; rb++) {
#pragma unroll
            for (int nb = 0; nb < 8; nb++) {
                float2 kk = *(const float2*)&ksq[8 * nb + 2 * (t & 3)];
                float c0 = -CEXP * (qs[rb][0] + kk.x);
                float c1 = -CEXP * (qs[rb][0] + kk.y);
                float c2 = -CEXP * (qs[rb][1] + kk.x);
                float c3 = -CEXP * (qs[rb][1] + kk.y);
                float p0 = ex2(fminf(fmaf(s[rb][nb][0], 2.f * CEXP, c0), 0.f));
                float p1 = ex2(fminf(fmaf(s[rb][nb][1], 2.f * CEXP, c1), 0.f));
                float p2 = ex2(fminf(fmaf(s[rb][nb][2], 2.f * CEXP, c2), 0.f));
                float p3 = ex2(fminf(fmaf(s[rb][nb][3], 2.f * CEXP, c3), 0.f));
                if (diag) {
                    int nE = n0 + 8 * nb + 2 * (t & 3);
                    if (nE     > m_r[rb][0]) p0 = 0.f;
                    if (nE + 1 > m_r[rb][0]) p1 = 0.f;
                    if (nE     > m_r[rb][1]) p2 = 0.f;
                    if (nE + 1 > m_r[rb][1]) p3 = 0.f;
                }
                l[rb][0] += p0 + p1;
                l[rb][1] += p2 + p3;
                s[rb][nb][0] = p0; s[rb][nb][1] = p1;
                s[rb][nb][2] = p2; s[rb][nb][3] = p3;
            }
        }

        // ---- O += P.V : per (g, rb), ping-pong prefetched ldsm4t ----
#pragma unroll
        for (int g = 0; g < 2; g++) {
#pragma unroll
            for (int rb = 0; rb < 2; rb++) {
                u32 pha[2][4], pla[2][4];
#pragma unroll
                for (int c = 0; c < 2; c++) {
                    const float* f0 = s[rb][2 * (2*g + c)];
                    const float* f1 = s[rb][2 * (2*g + c) + 1];
                    __nv_bfloat162 H0 = __floats2bfloat162_rn(f0[0], f0[1]);
                    __nv_bfloat162 H1 = __floats2bfloat162_rn(f0[2], f0[3]);
                    __nv_bfloat162 H2 = __floats2bfloat162_rn(f1[0], f1[1]);
                    __nv_bfloat162 H3 = __floats2bfloat162_rn(f1[2], f1[3]);
                    float2 g0 = __bfloat1622float2(H0);
                    float2 g1 = __bfloat1622float2(H1);
                    float2 g2 = __bfloat1622float2(H2);
                    float2 g3 = __bfloat1622float2(H3);
                    pha[c][0] = bits2(H0); pha[c][1] = bits2(H1);
                    pha[c][2] = bits2(H2); pha[c][3] = bits2(H3);
                    pla[c][0] = bits2(__floats2bfloat162_rn(f0[0]-g0.x, f0[1]-g0.y));
                    pla[c][1] = bits2(__floats2bfloat162_rn(f0[2]-g1.x, f0[3]-g1.y));
                    pla[c][2] = bits2(__floats2bfloat162_rn(f1[0]-g2.x, f1[1]-g2.y));
                    pla[c][3] = bits2(__floats2bfloat162_rn(f1[2]-g3.x, f1[3]-g3.y));
                }
                const u32 vrow = cb + B_VH +
                    (u32)(((32 * g + ((t >> 3) << 3) + (t & 7)) * LDH) * 2);
                u32 vh[2][4], vl[2][4];
                ldsm4t(vrow, vh[0]);
                ldsm4t(vrow + MAT, vl[0]);
#pragma unroll
                for (int nd = 0; nd < 8; nd++) {
                    const int cur = nd & 1;
                    if (nd < 7) {
                        ldsm4t(vrow + (u32)((8 * (nd + 1)) * 2), vh[cur ^ 1]);
                        ldsm4t(vrow + (u32)((8 * (nd + 1)) * 2) + MAT, vl[cur ^ 1]);
                    }
                    mma16816(o[rb][nd], pha[0], vh[cur][0], vh[cur][1]);
                    mma16816(o[rb][nd], pha[1], vh[cur][2], vh[cur][3]);
                    mma16816(o[rb][nd], pha[0], vl[cur][0], vl[cur][1]);
                    mma16816(o[rb][nd], pha[1], vl[cur][2], vl[cur][3]);
                    mma16816(o[rb][nd], pla[0], vh[cur][0], vh[cur][1]);
                    mma16816(o[rb][nd], pla[1], vh[cur][2], vh[cur][3]);
                }
            }
        }
    }

    // ---- reduce l across the 4-lane quad sharing each row ----
#pragma unroll
    for (int rb = 0; rb < 2; rb++) {
#pragma unroll
        for (int h = 0; h < 2; h++) {
            float lv = l[rb][h];
            lv += __shfl_xor_sync(0xffffffffu, lv, 1);
            lv += __shfl_xor_sync(0xffffffffu, lv, 2);
            l[rb][h] = lv;
        }
    }

    // ---- write O ----
#pragma unroll
    for (int rb = 0; rb < 2; rb++) {
        const float inv0 = 1.0f / l[rb][0];
        const float inv1 = 1.0f / l[rb][1];
#pragma unroll
        for (int nd = 0; nd < 8; nd++) {
            int dcol = 8 * nd + 2 * (t & 3);
            *(float2*)&Oh[(size_t)m_r[rb][0] * D_ + dcol] =
                make_float2(o[rb][nd][0] * inv0, o[rb][nd][1] * inv0);
            *(float2*)&Oh[(size_t)m_r[rb][1] * D_ + dcol] =
                make_float2(o[rb][nd][2] * inv1, o[rb][nd][3] * inv1);
        }
    }
}

extern "C" void kernel_launch(void* const* d_in, const int* in_sizes, int n_in,
                              void* d_out, int out_size)
{
    const float* q = (const float*)d_in[0];
    const float* k = (const float*)d_in[1];
    const float* v = (const float*)d_in[2];
    float* o = (float*)d_out;
    (void)in_sizes; (void)n_in; (void)out_size;

    prep_kernel<<<TOT4 / 256, 256>>>(k, v);

    cudaFuncSetAttribute(rbf_attn_mma,
                         cudaFuncAttributeMaxDynamicSharedMemorySize, SMEM_BYTES);

    dim3 grid(N_ / BM, 32);
    rbf_attn_mma<<<grid, NTH, SMEM_BYTES>>>(q, o);
}

// round 9
// speedup vs baseline: 1.1575x; 1.1575x over previous
#include <cuda_runtime.h>
#include <cuda_bf16.h>
#include <cstdint>

// RBF-kernel causal attention via warp-level mma.sync (bf16, hi/lo compensated).
// Round 9: R7 structure (BM=64, prep kernel, cp.async double buffer) with the
// per-tile chain split into 32-key halves:
//   QK(all) -> softmax(A) -> PV(A) -> softmax(B) -> PV(B)
// so softmax(B) ALU can overlap PV(A) tensor work. ksq prefetched to registers.
// B=2, H=16, N=2048, D=64. CTA: 64 queries, 4 warps, 64-key tiles.

#define N_   2048
#define D_   64
#define BM   64
#define BN   64
#define NTH  128
#define LDH  72                      // halves per bf16 smem row (144 B)
#define CEXP 0.18033688011112042f    // log2(e)/8

#define MAT    9216                  // 64 rows * 144 B
#define B_KH   0
#define B_KL   MAT
#define B_VH   (2*MAT)
#define B_VL   (3*MAT)
#define B_KSQ  (4*MAT)
#define BUF    (4*MAT + 256)         // 37120
#define OFF_QSQ (2*BUF)              // 74240
#define SMEM_BYTES (OFF_QSQ + 256)   // 74496

#define TOT4 (2*16*2048*16)          // float4 count per tensor

typedef uint32_t u32;

__device__ uint2 g_KH[TOT4];
__device__ uint2 g_KL[TOT4];
__device__ uint2 g_VH[TOT4];
__device__ uint2 g_VL[TOT4];
__device__ float g_ksq[2*16*2048];

__device__ __forceinline__ u32 smem_u32(const void* p) {
    u32 a;
    asm("{ .reg .u64 t; cvta.to.shared.u64 t, %1; cvt.u32.u64 %0, t; }"
        : "=r"(a) : "l"(p));
    return a;
}
__device__ __forceinline__ float ex2(float x) {
    float y; asm("ex2.approx.f32 %0, %1;" : "=f"(y) : "f"(x)); return y;
}
__device__ __forceinline__ void cp16(u32 saddr, const void* g) {
    asm volatile("cp.async.cg.shared.global [%0], [%1], 16;"
                 :: "r"(saddr), "l"(g) : "memory");
}
__device__ __forceinline__ void cp_commit() {
    asm volatile("cp.async.commit_group;" ::: "memory");
}
__device__ __forceinline__ void cp_wait0() {
    asm volatile("cp.async.wait_group 0;" ::: "memory");
}
__device__ __forceinline__ void ldsm4(u32 addr, u32 r[4]) {
    asm volatile("ldmatrix.sync.aligned.m8n8.x4.shared.b16 {%0,%1,%2,%3}, [%4];"
                 : "=r"(r[0]), "=r"(r[1]), "=r"(r[2]), "=r"(r[3]) : "r"(addr));
}
__device__ __forceinline__ void ldsm4t(u32 addr, u32 r[4]) {
    asm volatile("ldmatrix.sync.aligned.m8n8.x4.trans.shared.b16 {%0,%1,%2,%3}, [%4];"
                 : "=r"(r[0]), "=r"(r[1]), "=r"(r[2]), "=r"(r[3]) : "r"(addr));
}
__device__ __forceinline__ void mma16816(float d[4], const u32 a[4], u32 b0, u32 b1) {
    asm volatile(
        "mma.sync.aligned.m16n8k16.row.col.f32.bf16.bf16.f32 "
        "{%0,%1,%2,%3}, {%4,%5,%6,%7}, {%8,%9}, {%0,%1,%2,%3};"
        : "+f"(d[0]), "+f"(d[1]), "+f"(d[2]), "+f"(d[3])
        : "r"(a[0]), "r"(a[1]), "r"(a[2]), "r"(a[3]), "r"(b0), "r"(b1));
}
__device__ __forceinline__ u32 bits2(__nv_bfloat162 h) { return *(u32*)&h; }

__device__ __forceinline__ void split4(float4 v, uint2& hi, uint2& lo) {
    __nv_bfloat162 h0 = __floats2bfloat162_rn(v.x, v.y);
    __nv_bfloat162 h1 = __floats2bfloat162_rn(v.z, v.w);
    float2 f0 = __bfloat1622float2(h0);
    float2 f1 = __bfloat1622float2(h1);
    __nv_bfloat162 l0 = __floats2bfloat162_rn(v.x - f0.x, v.y - f0.y);
    __nv_bfloat162 l1 = __floats2bfloat162_rn(v.z - f1.x, v.w - f1.y);
    hi = make_uint2(bits2(h0), bits2(h1));
    lo = make_uint2(bits2(l0), bits2(l1));
}
__device__ __forceinline__ void cvt_store(char* smc, int off_hi, int off_lo, float4 v) {
    uint2 hi, lo;
    split4(v, hi, lo);
    *(uint2*)(smc + off_hi) = hi;
    *(uint2*)(smc + off_lo) = lo;
}

// ---------------- prep: f32 K/V -> bf16 hi/lo globals + ksq ----------------
__global__ void __launch_bounds__(256)
prep_kernel(const float* __restrict__ K, const float* __restrict__ V)
{
    const int i = blockIdx.x * 256 + threadIdx.x;     // float4 index
    float4 k = ((const float4*)K)[i];
    float4 v = ((const float4*)V)[i];
    uint2 hi, lo;
    split4(k, hi, lo);
    g_KH[i] = hi; g_KL[i] = lo;
    split4(v, hi, lo);
    g_VH[i] = hi; g_VL[i] = lo;

    float s = fmaf(k.x, k.x, fmaf(k.y, k.y, fmaf(k.z, k.z, k.w * k.w)));
    s += __shfl_xor_sync(0xffffffffu, s, 1, 16);
    s += __shfl_xor_sync(0xffffffffu, s, 2, 16);
    s += __shfl_xor_sync(0xffffffffu, s, 4, 16);
    s += __shfl_xor_sync(0xffffffffu, s, 8, 16);
    if ((threadIdx.x & 15) == 0) g_ksq[i >> 4] = s;
}

// cp.async one full key-tile (KH,KL,VH,VL + ksq) into smem buffer at dst
__device__ __forceinline__ void cp_tile(u32 dst, size_t rowbase, int tid)
{
    const char* khg = (const char*)g_KH + rowbase * 128;
    const char* klg = (const char*)g_KL + rowbase * 128;
    const char* vhg = (const char*)g_VH + rowbase * 128;
    const char* vlg = (const char*)g_VL + rowbase * 128;
#pragma unroll
    for (int i = 0; i < 4; i++) {
        int c   = i * 128 + tid;        // 0..511
        int row = c >> 3;
        int c8  = c & 7;
        u32 so  = (u32)(row * 144 + c8 * 16);
        size_t go = (size_t)row * 128 + (size_t)c8 * 16;
        cp16(dst + B_KH + so, khg + go);
        cp16(dst + B_KL + so, klg + go);
        cp16(dst + B_VH + so, vhg + go);
        cp16(dst + B_VL + so, vlg + go);
    }
    if (tid < 16)
        cp16(dst + B_KSQ + (u32)(tid * 16), (const char*)(g_ksq + rowbase) + tid * 16);
}

// ---------------- main kernel ----------------
__global__ void __launch_bounds__(NTH, 3)
rbf_attn_mma(const float* __restrict__ Qg, float* __restrict__ Og)
{
    extern __shared__ char smc[];
    const u32 sb  = smem_u32(smc);
    const int tid = threadIdx.x;
    const int w   = tid >> 5;
    const int t   = tid & 31;
    const int bh  = blockIdx.y;
    const int qt  = (gridDim.x - 1) - blockIdx.x;    // heavy tiles first
    const int m0  = qt * BM;
    const int nkt = qt + 1;

    const float* Qh = Qg + (size_t)bh * N_ * D_;
    float*       Oh = Og + (size_t)bh * N_ * D_;

    // ---- prologue: cp tile 0 into buffer 0 ----
    cp_tile(sb, (size_t)bh * N_, tid);
    cp_commit();

    // ---- stage Q (hi/lo bf16) into buffer 1, compute qsq ----
    {
        const float4* Q4 = (const float4*)(Qh + (size_t)m0 * D_);
#pragma unroll
        for (int i = 0; i < 8; i++) {
            int fidx = i * NTH + tid;
            int row  = fidx >> 4;
            int c4   = (fidx & 15) << 2;
            cvt_store(smc, BUF + B_KH + (row * LDH + c4) * 2,
                           BUF + B_KL + (row * LDH + c4) * 2, Q4[fidx]);
        }
        if (tid < BM) {
            float s = 0.f;
            const float4* Qr = (const float4*)(Qh + (size_t)(m0 + tid) * D_);
#pragma unroll
            for (int j = 0; j < 16; j++) {
                float4 v = Qr[j];
                s = fmaf(v.x, v.x, fmaf(v.y, v.y, fmaf(v.z, v.z, fmaf(v.w, v.w, s))));
            }
            ((float*)(smc + OFF_QSQ))[tid] = s;
        }
    }
    __syncthreads();

    // ---- extract Q A-fragments (persist in regs across all tiles) ----
    u32 qa[4][4], ql[4][4];
    {
        const int row = w * 16 + (((t >> 3) & 1) << 3) + (t & 7);
        const int cg  = (t >> 4) << 3;
#pragma unroll
        for (int kc = 0; kc < 4; kc++) {
            u32 addr = sb + BUF + B_KH + (u32)((row * LDH + 16 * kc + cg) * 2);
            ldsm4(addr, qa[kc]);
            ldsm4(addr + MAT, ql[kc]);
        }
    }
    const float q0 = ((float*)(smc + OFF_QSQ))[w * 16 + (t >> 2)];
    const float q1 = ((float*)(smc + OFF_QSQ))[w * 16 + (t >> 2) + 8];
    const int m_r0 = m0 + w * 16 + (t >> 2);
    const int m_r1 = m_r0 + 8;

    float o[8][4];
#pragma unroll
    for (int i = 0; i < 8; i++)
#pragma unroll
        for (int j = 0; j < 4; j++) o[i][j] = 0.f;
    float l0 = 0.f, l1 = 0.f;

    for (int kt = 0; kt < nkt; kt++) {
        const int n0 = kt * BN;
        const u32 cb = sb + (u32)((kt & 1) * BUF);
        const char* cc = smc + (size_t)((kt & 1) * BUF);
        const bool diag = (kt == qt);

        cp_wait0();
        __syncthreads();

        if (kt + 1 < nkt)
            cp_tile(sb + (u32)(((kt + 1) & 1) * BUF),
                    (size_t)bh * N_ + (size_t)(n0 + BN), tid);
        cp_commit();

        // ---- prefetch ksq pairs into registers ----
        float2 kkr[8];
        {
            const float* ksq = (const float*)(cc + B_KSQ);
#pragma unroll
            for (int nb = 0; nb < 8; nb++)
                kkr[nb] = *(const float2*)&ksq[8 * nb + 2 * (t & 3)];
        }

        // ---- S = Q.K^T (3 compensated passes, ping-pong ldsm) ----
        float s[8][4];
#pragma unroll
        for (int i = 0; i < 8; i++)
#pragma unroll
            for (int j = 0; j < 4; j++) s[i][j] = 0.f;

        u32 kb[2][4], kl[2][4];
        {
            u32 a0 = cb + (u32)((((t & 7)) * LDH + ((t >> 3) << 3)) * 2);
            ldsm4(a0, kb[0]);
            ldsm4(a0 + MAT, kl[0]);
        }
#pragma unroll
        for (int idx = 0; idx < 16; idx++) {
            const int cur = idx & 1;
            if (idx < 15) {
                const int nn = (idx + 1) >> 1, ng = (idx + 1) & 1;
                u32 an = cb + (u32)(((8 * nn + (t & 7)) * LDH
                                     + 32 * ng + ((t >> 3) << 3)) * 2);
                ldsm4(an, kb[cur ^ 1]);
                ldsm4(an + MAT, kl[cur ^ 1]);
            }
            const int nb = idx >> 1, g = idx & 1;
            mma16816(s[nb], qa[2*g],   kb[cur][0], kb[cur][1]);
            mma16816(s[nb], qa[2*g+1], kb[cur][2], kb[cur][3]);
            mma16816(s[nb], qa[2*g],   kl[cur][0], kl[cur][1]);
            mma16816(s[nb], qa[2*g+1], kl[cur][2], kl[cur][3]);
            mma16816(s[nb], ql[2*g],   kb[cur][0], kb[cur][1]);
            mma16816(s[nb], ql[2*g+1], kb[cur][2], kb[cur][3]);
        }

        // ==== process in 32-key halves: softmax(h) then PV(h). softmax of
        //      half 1 is independent of PV of half 0 -> overlappable. ====
#pragma unroll
        for (int h = 0; h < 2; h++) {
            // ---- softmax for nb in [4h, 4h+4) ----
#pragma unroll
            for (int nb = 4 * h; nb < 4 * h + 4; nb++) {
                float2 kk = kkr[nb];
                float c0 = -CEXP * (q0 + kk.x);
                float c1 = -CEXP * (q0 + kk.y);
                float c2 = -CEXP * (q1 + kk.x);
                float c3 = -CEXP * (q1 + kk.y);
                float p0 = ex2(fminf(fmaf(s[nb][0], 2.f * CEXP, c0), 0.f));
                float p1 = ex2(fminf(fmaf(s[nb][1], 2.f * CEXP, c1), 0.f));
                float p2 = ex2(fminf(fmaf(s[nb][2], 2.f * CEXP, c2), 0.f));
                float p3 = ex2(fminf(fmaf(s[nb][3], 2.f * CEXP, c3), 0.f));
                if (diag) {
                    int nE = n0 + 8 * nb + 2 * (t & 3);
                    if (nE     > m_r0) p0 = 0.f;
                    if (nE + 1 > m_r0) p1 = 0.f;
                    if (nE     > m_r1) p2 = 0.f;
                    if (nE + 1 > m_r1) p3 = 0.f;
                }
                l0 += p0 + p1;
                l1 += p2 + p3;
                s[nb][0] = p0; s[nb][1] = p1;
                s[nb][2] = p2; s[nb][3] = p3;
            }

            // ---- PV for this half (g = h): cvt P, then 48 MMAs ----
            u32 pha[2][4], pla[2][4];
#pragma unroll
            for (int c = 0; c < 2; c++) {
                const float* f0 = s[2 * (2*h + c)];
                const float* f1 = s[2 * (2*h + c) + 1];
                __nv_bfloat162 H0 = __floats2bfloat162_rn(f0[0], f0[1]);
                __nv_bfloat162 H1 = __floats2bfloat162_rn(f0[2], f0[3]);
                __nv_bfloat162 H2 = __floats2bfloat162_rn(f1[0], f1[1]);
                __nv_bfloat162 H3 = __floats2bfloat162_rn(f1[2], f1[3]);
                float2 g0 = __bfloat1622float2(H0);
                float2 g1 = __bfloat1622float2(H1);
                float2 g2 = __bfloat1622float2(H2);
                float2 g3 = __bfloat1622float2(H3);
                pha[c][0] = bits2(H0); pha[c][1] = bits2(H1);
                pha[c][2] = bits2(H2); pha[c][3] = bits2(H3);
                pla[c][0] = bits2(__floats2bfloat162_rn(f0[0]-g0.x, f0[1]-g0.y));
                pla[c][1] = bits2(__floats2bfloat162_rn(f0[2]-g1.x, f0[3]-g1.y));
                pla[c][2] = bits2(__floats2bfloat162_rn(f1[0]-g2.x, f1[1]-g2.y));
                pla[c][3] = bits2(__floats2bfloat162_rn(f1[2]-g3.x, f1[3]-g3.y));
            }
            const u32 vrow = cb + B_VH +
                (u32)(((32 * h + ((t >> 3) << 3) + (t & 7)) * LDH) * 2);
            u32 vh[2][4], vl[2][4];
            ldsm4t(vrow, vh[0]);
            ldsm4t(vrow + MAT, vl[0]);
#pragma unroll
            for (int nd = 0; nd < 8; nd++) {
                const int cur = nd & 1;
                if (nd < 7) {
                    ldsm4t(vrow + (u32)((8 * (nd + 1)) * 2), vh[cur ^ 1]);
                    ldsm4t(vrow + (u32)((8 * (nd + 1)) * 2) + MAT, vl[cur ^ 1]);
                }
                mma16816(o[nd], pha[0], vh[cur][0], vh[cur][1]);
                mma16816(o[nd], pha[1], vh[cur][2], vh[cur][3]);
                mma16816(o[nd], pha[0], vl[cur][0], vl[cur][1]);
                mma16816(o[nd], pha[1], vl[cur][2], vl[cur][3]);
                mma16816(o[nd], pla[0], vh[cur][0], vh[cur][1]);
                mma16816(o[nd], pla[1], vh[cur][2], vh[cur][3]);
            }
        }
    }

    // ---- reduce l across the 4-lane quad sharing each row ----
    l0 += __shfl_xor_sync(0xffffffffu, l0, 1);
    l0 += __shfl_xor_sync(0xffffffffu, l0, 2);
    l1 += __shfl_xor_sync(0xffffffffu, l1, 1);
    l1 += __shfl_xor_sync(0xffffffffu, l1, 2);
    const float inv0 = 1.0f / l0;
    const float inv1 = 1.0f / l1;

    // ---- write O ----
#pragma unroll
    for (int nd = 0; nd < 8; nd++) {
        int dcol = 8 * nd + 2 * (t & 3);
        *(float2*)&Oh[(size_t)m_r0 * D_ + dcol] =
            make_float2(o[nd][0] * inv0, o[nd][1] * inv0);
        *(float2*)&Oh[(size_t)m_r1 * D_ + dcol] =
            make_float2(o[nd][2] * inv1, o[nd][3] * inv1);
    }
}

extern "C" void kernel_launch(void* const* d_in, const int* in_sizes, int n_in,
                              void* d_out, int out_size)
{
    const float* q = (const float*)d_in[0];
    const float* k = (const float*)d_in[1];
    const float* v = (const float*)d_in[2];
    float* o = (float*)d_out;
    (void)in_sizes; (void)n_in; (void)out_size;

    prep_kernel<<<TOT4 / 256, 256>>>(k, v);

    cudaFuncSetAttribute(rbf_attn_mma,
                         cudaFuncAttributeMaxDynamicSharedMemorySize, SMEM_BYTES);

    dim3 grid(N_ / BM, 32);
    rbf_attn_mma<<<grid, NTH, SMEM_BYTES>>>(q, o);
}

// round 10
// speedup vs baseline: 1.1720x; 1.0125x over previous
#include <cuda_runtime.h>
#include <cuda_bf16.h>
#include <cstdint>

// RBF-kernel causal attention via warp-level mma.sync (bf16, hi/lo compensated).
// Round 10: R9 + 2-way accumulator interleave in both GEMMs (pair of nb/nd
// chains alternated per issue) to break mma->mma scoreboard stalls.
// B=2, H=16, N=2048, D=64. CTA: 64 queries, 4 warps, 64-key tiles.

#define N_   2048
#define D_   64
#define BM   64
#define BN   64
#define NTH  128
#define LDH  72                      // halves per bf16 smem row (144 B)
#define CEXP 0.18033688011112042f    // log2(e)/8

#define MAT    9216                  // 64 rows * 144 B
#define B_KH   0
#define B_KL   MAT
#define B_VH   (2*MAT)
#define B_VL   (3*MAT)
#define B_KSQ  (4*MAT)
#define BUF    (4*MAT + 256)         // 37120
#define OFF_QSQ (2*BUF)              // 74240
#define SMEM_BYTES (OFF_QSQ + 256)   // 74496

#define TOT4 (2*16*2048*16)          // float4 count per tensor

typedef uint32_t u32;

__device__ uint2 g_KH[TOT4];
__device__ uint2 g_KL[TOT4];
__device__ uint2 g_VH[TOT4];
__device__ uint2 g_VL[TOT4];
__device__ float g_ksq[2*16*2048];

__device__ __forceinline__ u32 smem_u32(const void* p) {
    u32 a;
    asm("{ .reg .u64 t; cvta.to.shared.u64 t, %1; cvt.u32.u64 %0, t; }"
        : "=r"(a) : "l"(p));
    return a;
}
__device__ __forceinline__ float ex2(float x) {
    float y; asm("ex2.approx.f32 %0, %1;" : "=f"(y) : "f"(x)); return y;
}
__device__ __forceinline__ void cp16(u32 saddr, const void* g) {
    asm volatile("cp.async.cg.shared.global [%0], [%1], 16;"
                 :: "r"(saddr), "l"(g) : "memory");
}
__device__ __forceinline__ void cp_commit() {
    asm volatile("cp.async.commit_group;" ::: "memory");
}
__device__ __forceinline__ void cp_wait0() {
    asm volatile("cp.async.wait_group 0;" ::: "memory");
}
__device__ __forceinline__ void ldsm4(u32 addr, u32 r[4]) {
    asm volatile("ldmatrix.sync.aligned.m8n8.x4.shared.b16 {%0,%1,%2,%3}, [%4];"
                 : "=r"(r[0]), "=r"(r[1]), "=r"(r[2]), "=r"(r[3]) : "r"(addr));
}
__device__ __forceinline__ void ldsm4t(u32 addr, u32 r[4]) {
    asm volatile("ldmatrix.sync.aligned.m8n8.x4.trans.shared.b16 {%0,%1,%2,%3}, [%4];"
                 : "=r"(r[0]), "=r"(r[1]), "=r"(r[2]), "=r"(r[3]) : "r"(addr));
}
__device__ __forceinline__ void mma16816(float d[4], const u32 a[4], u32 b0, u32 b1) {
    asm volatile(
        "mma.sync.aligned.m16n8k16.row.col.f32.bf16.bf16.f32 "
        "{%0,%1,%2,%3}, {%4,%5,%6,%7}, {%8,%9}, {%0,%1,%2,%3};"
        : "+f"(d[0]), "+f"(d[1]), "+f"(d[2]), "+f"(d[3])
        : "r"(a[0]), "r"(a[1]), "r"(a[2]), "r"(a[3]), "r"(b0), "r"(b1));
}
__device__ __forceinline__ u32 bits2(__nv_bfloat162 h) { return *(u32*)&h; }

__device__ __forceinline__ void split4(float4 v, uint2& hi, uint2& lo) {
    __nv_bfloat162 h0 = __floats2bfloat162_rn(v.x, v.y);
    __nv_bfloat162 h1 = __floats2bfloat162_rn(v.z, v.w);
    float2 f0 = __bfloat1622float2(h0);
    float2 f1 = __bfloat1622float2(h1);
    __nv_bfloat162 l0 = __floats2bfloat162_rn(v.x - f0.x, v.y - f0.y);
    __nv_bfloat162 l1 = __floats2bfloat162_rn(v.z - f1.x, v.w - f1.y);
    hi = make_uint2(bits2(h0), bits2(h1));
    lo = make_uint2(bits2(l0), bits2(l1));
}
__device__ __forceinline__ void cvt_store(char* smc, int off_hi, int off_lo, float4 v) {
    uint2 hi, lo;
    split4(v, hi, lo);
    *(uint2*)(smc + off_hi) = hi;
    *(uint2*)(smc + off_lo) = lo;
}

// ---------------- prep: f32 K/V -> bf16 hi/lo globals + ksq ----------------
__global__ void __launch_bounds__(256)
prep_kernel(const float* __restrict__ K, const float* __restrict__ V)
{
    const int i = blockIdx.x * 256 + threadIdx.x;     // float4 index
    float4 k = ((const float4*)K)[i];
    float4 v = ((const float4*)V)[i];
    uint2 hi, lo;
    split4(k, hi, lo);
    g_KH[i] = hi; g_KL[i] = lo;
    split4(v, hi, lo);
    g_VH[i] = hi; g_VL[i] = lo;

    float s = fmaf(k.x, k.x, fmaf(k.y, k.y, fmaf(k.z, k.z, k.w * k.w)));
    s += __shfl_xor_sync(0xffffffffu, s, 1, 16);
    s += __shfl_xor_sync(0xffffffffu, s, 2, 16);
    s += __shfl_xor_sync(0xffffffffu, s, 4, 16);
    s += __shfl_xor_sync(0xffffffffu, s, 8, 16);
    if ((threadIdx.x & 15) == 0) g_ksq[i >> 4] = s;
}

// cp.async one full key-tile (KH,KL,VH,VL + ksq) into smem buffer at dst
__device__ __forceinline__ void cp_tile(u32 dst, size_t rowbase, int tid)
{
    const char* khg = (const char*)g_KH + rowbase * 128;
    const char* klg = (const char*)g_KL + rowbase * 128;
    const char* vhg = (const char*)g_VH + rowbase * 128;
    const char* vlg = (const char*)g_VL + rowbase * 128;
#pragma unroll
    for (int i = 0; i < 4; i++) {
        int c   = i * 128 + tid;        // 0..511
        int row = c >> 3;
        int c8  = c & 7;
        u32 so  = (u32)(row * 144 + c8 * 16);
        size_t go = (size_t)row * 128 + (size_t)c8 * 16;
        cp16(dst + B_KH + so, khg + go);
        cp16(dst + B_KL + so, klg + go);
        cp16(dst + B_VH + so, vhg + go);
        cp16(dst + B_VL + so, vlg + go);
    }
    if (tid < 16)
        cp16(dst + B_KSQ + (u32)(tid * 16), (const char*)(g_ksq + rowbase) + tid * 16);
}

// ---------------- main kernel ----------------
__global__ void __launch_bounds__(NTH, 3)
rbf_attn_mma(const float* __restrict__ Qg, float* __restrict__ Og)
{
    extern __shared__ char smc[];
    const u32 sb  = smem_u32(smc);
    const int tid = threadIdx.x;
    const int w   = tid >> 5;
    const int t   = tid & 31;
    const int bh  = blockIdx.y;
    const int qt  = (gridDim.x - 1) - blockIdx.x;    // heavy tiles first
    const int m0  = qt * BM;
    const int nkt = qt + 1;

    const float* Qh = Qg + (size_t)bh * N_ * D_;
    float*       Oh = Og + (size_t)bh * N_ * D_;

    // ---- prologue: cp tile 0 into buffer 0 ----
    cp_tile(sb, (size_t)bh * N_, tid);
    cp_commit();

    // ---- stage Q (hi/lo bf16) into buffer 1, compute qsq ----
    {
        const float4* Q4 = (const float4*)(Qh + (size_t)m0 * D_);
#pragma unroll
        for (int i = 0; i < 8; i++) {
            int fidx = i * NTH + tid;
            int row  = fidx >> 4;
            int c4   = (fidx & 15) << 2;
            cvt_store(smc, BUF + B_KH + (row * LDH + c4) * 2,
                           BUF + B_KL + (row * LDH + c4) * 2, Q4[fidx]);
        }
        if (tid < BM) {
            float s = 0.f;
            const float4* Qr = (const float4*)(Qh + (size_t)(m0 + tid) * D_);
#pragma unroll
            for (int j = 0; j < 16; j++) {
                float4 v = Qr[j];
                s = fmaf(v.x, v.x, fmaf(v.y, v.y, fmaf(v.z, v.z, fmaf(v.w, v.w, s))));
            }
            ((float*)(smc + OFF_QSQ))[tid] = s;
        }
    }
    __syncthreads();

    // ---- extract Q A-fragments (persist in regs across all tiles) ----
    u32 qa[4][4], ql[4][4];
    {
        const int row = w * 16 + (((t >> 3) & 1) << 3) + (t & 7);
        const int cg  = (t >> 4) << 3;
#pragma unroll
        for (int kc = 0; kc < 4; kc++) {
            u32 addr = sb + BUF + B_KH + (u32)((row * LDH + 16 * kc + cg) * 2);
            ldsm4(addr, qa[kc]);
            ldsm4(addr + MAT, ql[kc]);
        }
    }
    const float q0 = ((float*)(smc + OFF_QSQ))[w * 16 + (t >> 2)];
    const float q1 = ((float*)(smc + OFF_QSQ))[w * 16 + (t >> 2) + 8];
    const int m_r0 = m0 + w * 16 + (t >> 2);
    const int m_r1 = m_r0 + 8;

    float o[8][4];
#pragma unroll
    for (int i = 0; i < 8; i++)
#pragma unroll
        for (int j = 0; j < 4; j++) o[i][j] = 0.f;
    float l0 = 0.f, l1 = 0.f;

    for (int kt = 0; kt < nkt; kt++) {
        const int n0 = kt * BN;
        const u32 cb = sb + (u32)((kt & 1) * BUF);
        const char* cc = smc + (size_t)((kt & 1) * BUF);
        const bool diag = (kt == qt);

        cp_wait0();
        __syncthreads();

        if (kt + 1 < nkt)
            cp_tile(sb + (u32)(((kt + 1) & 1) * BUF),
                    (size_t)bh * N_ + (size_t)(n0 + BN), tid);
        cp_commit();

        // ---- prefetch ksq pairs into registers ----
        float2 kkr[8];
        {
            const float* ksq = (const float*)(cc + B_KSQ);
#pragma unroll
            for (int nb = 0; nb < 8; nb++)
                kkr[nb] = *(const float2*)&ksq[8 * nb + 2 * (t & 3)];
        }

        // ---- S = Q.K^T : pairs of nb chains, interleaved MMA issue ----
        float s[8][4];
#pragma unroll
        for (int i = 0; i < 8; i++)
#pragma unroll
            for (int j = 0; j < 4; j++) s[i][j] = 0.f;

        u32 kb[2][4], kl[2][4];      // fragments for the pair's two nb rows
#pragma unroll
        for (int it = 0; it < 8; it++) {
            const int g = it >> 2, pair = it & 3;
            const int nb0 = 2 * pair, nb1 = nb0 + 1;
            {
                u32 a0 = cb + (u32)(((8 * nb0 + (t & 7)) * LDH
                                     + 32 * g + ((t >> 3) << 3)) * 2);
                u32 a1 = a0 + (u32)(8 * LDH * 2);
                ldsm4(a0, kb[0]);
                ldsm4(a1, kb[1]);
                ldsm4(a0 + MAT, kl[0]);
                ldsm4(a1 + MAT, kl[1]);
            }
            mma16816(s[nb0], qa[2*g],   kb[0][0], kb[0][1]);
            mma16816(s[nb1], qa[2*g],   kb[1][0], kb[1][1]);
            mma16816(s[nb0], qa[2*g+1], kb[0][2], kb[0][3]);
            mma16816(s[nb1], qa[2*g+1], kb[1][2], kb[1][3]);
            mma16816(s[nb0], qa[2*g],   kl[0][0], kl[0][1]);
            mma16816(s[nb1], qa[2*g],   kl[1][0], kl[1][1]);
            mma16816(s[nb0], qa[2*g+1], kl[0][2], kl[0][3]);
            mma16816(s[nb1], qa[2*g+1], kl[1][2], kl[1][3]);
            mma16816(s[nb0], ql[2*g],   kb[0][0], kb[0][1]);
            mma16816(s[nb1], ql[2*g],   kb[1][0], kb[1][1]);
            mma16816(s[nb0], ql[2*g+1], kb[0][2], kb[0][3]);
            mma16816(s[nb1], ql[2*g+1], kb[1][2], kb[1][3]);
        }

        // ==== 32-key halves: softmax(h) then PV(h) ====
#pragma unroll
        for (int h = 0; h < 2; h++) {
            // ---- softmax for nb in [4h, 4h+4) ----
#pragma unroll
            for (int nb = 4 * h; nb < 4 * h + 4; nb++) {
                float2 kk = kkr[nb];
                float c0 = -CEXP * (q0 + kk.x);
                float c1 = -CEXP * (q0 + kk.y);
                float c2 = -CEXP * (q1 + kk.x);
                float c3 = -CEXP * (q1 + kk.y);
                float p0 = ex2(fminf(fmaf(s[nb][0], 2.f * CEXP, c0), 0.f));
                float p1 = ex2(fminf(fmaf(s[nb][1], 2.f * CEXP, c1), 0.f));
                float p2 = ex2(fminf(fmaf(s[nb][2], 2.f * CEXP, c2), 0.f));
                float p3 = ex2(fminf(fmaf(s[nb][3], 2.f * CEXP, c3), 0.f));
                if (diag) {
                    int nE = n0 + 8 * nb + 2 * (t & 3);
                    if (nE     > m_r0) p0 = 0.f;
                    if (nE + 1 > m_r0) p1 = 0.f;
                    if (nE     > m_r1) p2 = 0.f;
                    if (nE + 1 > m_r1) p3 = 0.f;
                }
                l0 += p0 + p1;
                l1 += p2 + p3;
                s[nb][0] = p0; s[nb][1] = p1;
                s[nb][2] = p2; s[nb][3] = p3;
            }

            // ---- PV for this half: cvt P, then nd-pairs interleaved ----
            u32 pha[2][4], pla[2][4];
#pragma unroll
            for (int c = 0; c < 2; c++) {
                const float* f0 = s[2 * (2*h + c)];
                const float* f1 = s[2 * (2*h + c) + 1];
                __nv_bfloat162 H0 = __floats2bfloat162_rn(f0[0], f0[1]);
                __nv_bfloat162 H1 = __floats2bfloat162_rn(f0[2], f0[3]);
                __nv_bfloat162 H2 = __floats2bfloat162_rn(f1[0], f1[1]);
                __nv_bfloat162 H3 = __floats2bfloat162_rn(f1[2], f1[3]);
                float2 g0 = __bfloat1622float2(H0);
                float2 g1 = __bfloat1622float2(H1);
                float2 g2 = __bfloat1622float2(H2);
                float2 g3 = __bfloat1622float2(H3);
                pha[c][0] = bits2(H0); pha[c][1] = bits2(H1);
                pha[c][2] = bits2(H2); pha[c][3] = bits2(H3);
                pla[c][0] = bits2(__floats2bfloat162_rn(f0[0]-g0.x, f0[1]-g0.y));
                pla[c][1] = bits2(__floats2bfloat162_rn(f0[2]-g1.x, f0[3]-g1.y));
                pla[c][2] = bits2(__floats2bfloat162_rn(f1[0]-g2.x, f1[1]-g2.y));
                pla[c][3] = bits2(__floats2bfloat162_rn(f1[2]-g3.x, f1[3]-g3.y));
            }
            const u32 vrow = cb + B_VH +
                (u32)(((32 * h + ((t >> 3) << 3) + (t & 7)) * LDH) * 2);
            u32 vh[2][4], vl[2][4];
#pragma unroll
            for (int pr = 0; pr < 4; pr++) {
                const int nd0 = 2 * pr, nd1 = nd0 + 1;
                {
                    u32 a0 = vrow + (u32)((8 * nd0) * 2);
                    u32 a1 = vrow + (u32)((8 * nd1) * 2);
                    ldsm4t(a0, vh[0]);
                    ldsm4t(a1, vh[1]);
                    ldsm4t(a0 + MAT, vl[0]);
                    ldsm4t(a1 + MAT, vl[1]);
                }
                mma16816(o[nd0], pha[0], vh[0][0], vh[0][1]);
                mma16816(o[nd1], pha[0], vh[1][0], vh[1][1]);
                mma16816(o[nd0], pha[1], vh[0][2], vh[0][3]);
                mma16816(o[nd1], pha[1], vh[1][2], vh[1][3]);
                mma16816(o[nd0], pha[0], vl[0][0], vl[0][1]);
                mma16816(o[nd1], pha[0], vl[1][0], vl[1][1]);
                mma16816(o[nd0], pha[1], vl[0][2], vl[0][3]);
                mma16816(o[nd1], pha[1], vl[1][2], vl[1][3]);
                mma16816(o[nd0], pla[0], vh[0][0], vh[0][1]);
                mma16816(o[nd1], pla[0], vh[1][0], vh[1][1]);
                mma16816(o[nd0], pla[1], vh[0][2], vh[0][3]);
                mma16816(o[nd1], pla[1], vh[1][2], vh[1][3]);
            }
        }
    }

    // ---- reduce l across the 4-lane quad sharing each row ----
    l0 += __shfl_xor_sync(0xffffffffu, l0, 1);
    l0 += __shfl_xor_sync(0xffffffffu, l0, 2);
    l1 += __shfl_xor_sync(0xffffffffu, l1, 1);
    l1 += __shfl_xor_sync(0xffffffffu, l1, 2);
    const float inv0 = 1.0f / l0;
    const float inv1 = 1.0f / l1;

    // ---- write O ----
#pragma unroll
    for (int nd = 0; nd < 8; nd++) {
        int dcol = 8 * nd + 2 * (t & 3);
        *(float2*)&Oh[(size_t)m_r0 * D_ + dcol] =
            make_float2(o[nd][0] * inv0, o[nd][1] * inv0);
        *(float2*)&Oh[(size_t)m_r1 * D_ + dcol] =
            make_float2(o[nd][2] * inv1, o[nd][3] * inv1);
    }
}

extern "C" void kernel_launch(void* const* d_in, const int* in_sizes, int n_in,
                              void* d_out, int out_size)
{
    const float* q = (const float*)d_in[0];
    const float* k = (const float*)d_in[1];
    const float* v = (const float*)d_in[2];
    float* o = (float*)d_out;
    (void)in_sizes; (void)n_in; (void)out_size;

    prep_kernel<<<TOT4 / 256, 256>>>(k, v);

    cudaFuncSetAttribute(rbf_attn_mma,
                         cudaFuncAttributeMaxDynamicSharedMemorySize, SMEM_BYTES);

    dim3 grid(N_ / BM, 32);
    rbf_attn_mma<<<grid, NTH, SMEM_BYTES>>>(q, o);
}